// round 15
// baseline (speedup 1.0000x reference)
#include <cuda_runtime.h>
#include <cuda_bf16.h>
#include <math.h>

// ---------------------------------------------------------------------------
// Problem constants
// ---------------------------------------------------------------------------
#define CI      512
#define CO      512
#define HH      50
#define WW      50
#define NPIX    2500
#define HP      52
#define WP      52
#define PADPIX  2704          // 52*52
#define KDIM    4608          // 512*9
#define NA      22500         // 2500*9 anchors
#define NPRE    12000
#define NWORD   188           // ceil(12000/64) 64-bit words
#define NWORD32 376           // 32-bit words per mask row
#define NPOST   2000
#define NHEADOC 54            // 36 loc + 18 score channels

// output layout (flattened tuple, all f32):
// rpn_locs [22500,4] | rpn_scores [22500,2] | rois [2000,4] | roi_indices [2000] | anchor [22500,4]
#define OUT_LOCS   0
#define OUT_SCORES 90000
#define OUT_ROIS   135000
#define OUT_IDX    143000
#define OUT_ANCH   145000

// ---------------------------------------------------------------------------
// Scratch (__device__ globals — allocation is forbidden)
// ---------------------------------------------------------------------------
__device__ float g_xpad[CI * PADPIX];
__device__ float g_Wt[CO * KDIM];     // W1 transposed to [co][(ky*3+kx)*512+ci]
__device__ float g_h[CO * NPIX];
__device__ float g_fg[NA];
__device__ float g_ry1[NA], g_rx1[NA], g_ry2[NA], g_rx2[NA];
__device__ int   g_valid[NA];
__device__ unsigned long long g_key[NA];
__device__ int   g_hist[65536];
__device__ int   g_cnt[65536];
__device__ int   g_bsum[256];
__device__ int   g_boff[256];
__device__ int   g_offs[65536];
__device__ unsigned long long g_slotkey[NA];
__device__ int   g_slotidx[NA];
__device__ float g_sy1[NPRE], g_sx1[NPRE], g_sy2[NPRE], g_sx2[NPRE];
__device__ int   g_svalid[NPRE];
__device__ __align__(8) unsigned g_mask32[(size_t)NPRE * NWORD32];

// ---------------------------------------------------------------------------
// 0) transpose W1[co][ci][ky][kx] -> g_Wt[co][kyx*512+ci]  (im2col k-order)
// ---------------------------------------------------------------------------
__global__ void k_wt(const float* __restrict__ W1) {
    int i = blockIdx.x * blockDim.x + threadIdx.x;
    if (i >= CO * KDIM) return;
    int co = i / KDIM;
    int k  = i - co * KDIM;       // k' = kyx*512 + ci
    int kyx = k >> 9;
    int ci  = k & 511;
    g_Wt[i] = W1[co * KDIM + ci * 9 + kyx];
}

// ---------------------------------------------------------------------------
// 1) zero-pad input  x[512][50][50] -> g_xpad[512][52][52]
// ---------------------------------------------------------------------------
__global__ void k_pad(const float* __restrict__ x) {
    int idx = blockIdx.x * blockDim.x + threadIdx.x;
    if (idx >= CI * PADPIX) return;
    int ci = idx / PADPIX;
    int r  = idx - ci * PADPIX;
    int yy = r / WP;
    int xx = r - yy * WP;
    float v = 0.f;
    if (yy >= 1 && yy <= HH && xx >= 1 && xx <= WW)
        v = x[ci * NPIX + (yy - 1) * WW + (xx - 1)];
    g_xpad[idx] = v;
}

// ---------------------------------------------------------------------------
// 2) conv1 3x3 512->512, fp32 implicit GEMM + bias + ReLU.
//    Reference-replicating reduction (CPU SIMD dot hypothesis):
//    k in im2col order k' = (ky*3+kx)*512 + ci (ci innermost, ascending);
//    EIGHT interleaved accumulator chains, chain r = { k' : k' mod 8 == r },
//    strict sequential FMA within each chain; final combine:
//    q_l = C_l + C_{l+4} (lanewise v0+v1), total = ((q0+q1)+q2)+q3.
//    Tile 32co x 32px, 128 threads, 4co x 2px x 8 chains per thread.
// ---------------------------------------------------------------------------
__global__ void __launch_bounds__(128) k_conv1(const float* __restrict__ b1) {
    __shared__ float As[16][32];
    __shared__ float Bs[16][32];
    int t   = threadIdx.x;
    int pb  = blockIdx.x * 32;
    int cob = blockIdx.y * 32;
    int tco = (t >> 4) * 4;      // 0..28 step 4
    int tpx = (t & 15) * 2;      // 0..30 step 2
    int kl   = t >> 3;           // 0..15
    int pseg = (t & 7) * 4;      // 0..28

    float acc[4][2][8];
#pragma unroll
    for (int i = 0; i < 4; ++i)
#pragma unroll
        for (int j = 0; j < 2; ++j)
#pragma unroll
            for (int r = 0; r < 8; ++r) acc[i][j][r] = 0.f;

    for (int kb = 0; kb < KDIM; kb += 16) {
        // stage A: g_Wt[co][k'] (contiguous in k'), 128 x float4
        {
            int col = t >> 2;            // co local 0..31
            int kq  = (t & 3) << 2;      // k local 0,4,8,12
            float4 v = *(const float4*)(g_Wt + (size_t)(cob + col) * KDIM + kb + kq);
            As[kq + 0][col] = v.x;
            As[kq + 1][col] = v.y;
            As[kq + 2][col] = v.z;
            As[kq + 3][col] = v.w;
        }
        // stage B: gather from padded image; 16-block lies in one (ky,kx) tap
        {
            int kyx = kb >> 9;
            int ci  = (kb & 511) + kl;
            int ky  = kyx / 3;
            int kx  = kyx - ky * 3;
            const float* base = g_xpad + ci * PADPIX + ky * WP + kx;
#pragma unroll
            for (int jj = 0; jj < 4; ++jj) {
                int p = pb + pseg + jj;
                float v = 0.f;
                if (p < NPIX) {
                    int y  = p / WW;
                    int xx = p - y * WW;
                    v = base[y * WP + xx];
                }
                Bs[kl][pseg + jj] = v;
            }
        }
        __syncthreads();
#pragma unroll
        for (int kk = 0; kk < 16; ++kk) {
            float a0 = As[kk][tco + 0];
            float a1 = As[kk][tco + 1];
            float a2 = As[kk][tco + 2];
            float a3 = As[kk][tco + 3];
            float bb0 = Bs[kk][tpx + 0];
            float bb1 = Bs[kk][tpx + 1];
            const int r = kk & 7;        // chain id = k' mod 8 (kb % 16 == 0)
            acc[0][0][r] = __fmaf_rn(a0, bb0, acc[0][0][r]);
            acc[0][1][r] = __fmaf_rn(a0, bb1, acc[0][1][r]);
            acc[1][0][r] = __fmaf_rn(a1, bb0, acc[1][0][r]);
            acc[1][1][r] = __fmaf_rn(a1, bb1, acc[1][1][r]);
            acc[2][0][r] = __fmaf_rn(a2, bb0, acc[2][0][r]);
            acc[2][1][r] = __fmaf_rn(a2, bb1, acc[2][1][r]);
            acc[3][0][r] = __fmaf_rn(a3, bb0, acc[3][0][r]);
            acc[3][1][r] = __fmaf_rn(a3, bb1, acc[3][1][r]);
        }
        __syncthreads();
    }
#pragma unroll
    for (int i = 0; i < 4; ++i) {
        int co = cob + tco + i;
        float bb = b1[co];
#pragma unroll
        for (int j = 0; j < 2; ++j) {
            int pg = pb + tpx + j;
            if (pg < NPIX) {
                float q0 = __fadd_rn(acc[i][j][0], acc[i][j][4]);
                float q1 = __fadd_rn(acc[i][j][1], acc[i][j][5]);
                float q2 = __fadd_rn(acc[i][j][2], acc[i][j][6]);
                float q3 = __fadd_rn(acc[i][j][3], acc[i][j][7]);
                float s  = __fadd_rn(__fadd_rn(__fadd_rn(q0, q1), q2), q3);
                float v  = __fadd_rn(s, bb);
                g_h[(size_t)co * NPIX + pg] = fmaxf(v, 0.f);
            }
        }
    }
}

// ---------------------------------------------------------------------------
// 3) 1x1 heads (36 loc + 18 score channels): SAME 8-chain interleave over ci
//    (chain = ci mod 8), same combine; write transposed into d_out.
// ---------------------------------------------------------------------------
__global__ void __launch_bounds__(256) k_heads(const float* __restrict__ Wl,
                                               const float* __restrict__ bl,
                                               const float* __restrict__ Ws,
                                               const float* __restrict__ bs,
                                               float* __restrict__ out) {
    __shared__ float hs[32][33];
    int px0 = blockIdx.x * 32;
    int tx = threadIdx.x & 31;
    int ty = threadIdx.x >> 5;   // 0..7
    float acc[7][8];
#pragma unroll
    for (int o = 0; o < 7; ++o)
#pragma unroll
        for (int r = 0; r < 8; ++r) acc[o][r] = 0.f;

    for (int c0 = 0; c0 < CO; c0 += 32) {
        for (int r = ty; r < 32; r += 8) {
            int px = px0 + tx;
            hs[r][tx] = (px < NPIX) ? g_h[(size_t)(c0 + r) * NPIX + px] : 0.f;
        }
        __syncthreads();
#pragma unroll 4
        for (int r = 0; r < 32; ++r) {
            float hv = hs[r][tx];
            const int ch = r & 7;        // ci mod 8 (c0 % 32 == 0)
#pragma unroll
            for (int o = 0; o < 7; ++o) {
                int oc = ty + o * 8;
                if (oc < NHEADOC) {
                    float wv = (oc < 36) ? Wl[oc * CO + c0 + r]
                                         : Ws[(oc - 36) * CO + c0 + r];
                    acc[o][ch] = __fmaf_rn(hv, wv, acc[o][ch]);
                }
            }
        }
        __syncthreads();
    }
    int px = px0 + tx;
    if (px >= NPIX) return;
#pragma unroll
    for (int o = 0; o < 7; ++o) {
        int oc = ty + o * 8;
        if (oc >= NHEADOC) continue;
        float q0 = __fadd_rn(acc[o][0], acc[o][4]);
        float q1 = __fadd_rn(acc[o][1], acc[o][5]);
        float q2 = __fadd_rn(acc[o][2], acc[o][6]);
        float q3 = __fadd_rn(acc[o][3], acc[o][7]);
        float sum = __fadd_rn(__fadd_rn(__fadd_rn(q0, q1), q2), q3);
        if (oc < 36) {
            float v = __fadd_rn(sum, bl[oc]);
            int a = oc >> 2, j = oc & 3;
            out[OUT_LOCS + (px * 9 + a) * 4 + j] = v;
        } else {
            int sdx = oc - 36;
            float v = __fadd_rn(sum, bs[sdx]);
            int a = sdx >> 1, b2 = sdx & 1;
            out[OUT_SCORES + (px * 9 + a) * 2 + b2] = v;
        }
    }
}

// ---------------------------------------------------------------------------
// 4) softmax fg scores
// ---------------------------------------------------------------------------
__global__ void k_fg(const float* __restrict__ out) {
    int i = blockIdx.x * blockDim.x + threadIdx.x;
    if (i >= NA) return;
    float s0 = out[OUT_SCORES + 2 * i];
    float s1 = out[OUT_SCORES + 2 * i + 1];
    float m = fmaxf(s0, s1);
    float e0 = expf(__fsub_rn(s0, m));
    float e1 = expf(__fsub_rn(s1, m));
    g_fg[i] = __fdiv_rn(e1, __fadd_rn(e0, e1));
}

// ---------------------------------------------------------------------------
// 5) anchors (fp64 to bit-match numpy's promotion chain)
// ---------------------------------------------------------------------------
__global__ void k_anchor(float* __restrict__ out) {
    int i = blockIdx.x * blockDim.x + threadIdx.x;
    if (i >= NA) return;
    int p = i / 9, a = i - p * 9;
    int y = p / WW, x = p - y * WW;
    int ra = a / 3, sc = a - ra * 3;
    double ratio = (ra == 0) ? 0.5 : (ra == 1) ? 1.0 : 2.0;
    double scale = (sc == 0) ? 8.0 : (sc == 1) ? 16.0 : 32.0;
    double hh_ = 16.0 * scale * sqrt(ratio);
    double ww_ = 16.0 * scale * sqrt(1.0 / ratio);
    float b0  = (float)(8.0 - hh_ * 0.5);
    float b1_ = (float)(8.0 - ww_ * 0.5);
    float b2  = (float)(8.0 + hh_ * 0.5);
    float b3  = (float)(8.0 + ww_ * 0.5);
    double sy = (double)(y * 16);
    double sx = (double)(x * 16);
    out[OUT_ANCH + i * 4 + 0] = (float)(sy + (double)b0);
    out[OUT_ANCH + i * 4 + 1] = (float)(sx + (double)b1_);
    out[OUT_ANCH + i * 4 + 2] = (float)(sy + (double)b2);
    out[OUT_ANCH + i * 4 + 3] = (float)(sx + (double)b3);
}

// ---------------------------------------------------------------------------
// 6) zero histograms
// ---------------------------------------------------------------------------
__global__ void k_zero() {
    int i = blockIdx.x * blockDim.x + threadIdx.x;
    if (i < 65536) { g_hist[i] = 0; g_cnt[i] = 0; }
}

// ---------------------------------------------------------------------------
// 7) decode boxes + clip + valid + sort keys + histogram.
// ---------------------------------------------------------------------------
__global__ void k_decode(const float* __restrict__ out) {
    int i = blockIdx.x * blockDim.x + threadIdx.x;
    if (i >= NA) return;
    float a0 = out[OUT_ANCH + i * 4 + 0];
    float a1 = out[OUT_ANCH + i * 4 + 1];
    float a2 = out[OUT_ANCH + i * 4 + 2];
    float a3 = out[OUT_ANCH + i * 4 + 3];
    float dy = out[OUT_LOCS + i * 4 + 0];
    float dx = out[OUT_LOCS + i * 4 + 1];
    float dh = out[OUT_LOCS + i * 4 + 2];
    float dw = out[OUT_LOCS + i * 4 + 3];
    float sh = __fsub_rn(a2, a0);
    float sw = __fsub_rn(a3, a1);
    float cy = __fadd_rn(a0, __fmul_rn(0.5f, sh));
    float cx = __fadd_rn(a1, __fmul_rn(0.5f, sw));
    float ncy = __fadd_rn(__fmul_rn(dy, sh), cy);
    float ncx = __fadd_rn(__fmul_rn(dx, sw), cx);
    float nh = __fmul_rn(expf(dh), sh);
    float nw = __fmul_rn(expf(dw), sw);
    float y1 = __fsub_rn(ncy, __fmul_rn(0.5f, nh));
    float x1 = __fsub_rn(ncx, __fmul_rn(0.5f, nw));
    float y2 = __fadd_rn(ncy, __fmul_rn(0.5f, nh));
    float x2 = __fadd_rn(ncx, __fmul_rn(0.5f, nw));
    y1 = fminf(fmaxf(y1, 0.f), 800.f);
    x1 = fminf(fmaxf(x1, 0.f), 800.f);
    y2 = fminf(fmaxf(y2, 0.f), 800.f);
    x2 = fminf(fmaxf(x2, 0.f), 800.f);
    float hsz = __fsub_rn(y2, y1);
    float wsz = __fsub_rn(x2, x1);
    int valid = (hsz >= 16.f) && (wsz >= 16.f);
    g_ry1[i] = y1; g_rx1[i] = x1; g_ry2[i] = y2; g_rx2[i] = x2;
    g_valid[i] = valid;
    unsigned mf;
    if (valid) {
        unsigned f = __float_as_uint(g_fg[i]);
        mf = (f & 0x80000000u) ? ~f : (f | 0x80000000u);
    } else {
        mf = 0x40000000u - ((unsigned)i << 11);   // descending in i, < all valid
    }
    unsigned long long key =
        ((unsigned long long)mf << 32) | (unsigned long long)(NA - 1 - i);
    g_key[i] = key;
    atomicAdd(&g_hist[mf >> 16], 1);
}

// ---------------------------------------------------------------------------
// 8-10) descending exclusive scan of 65536-bucket histogram (3 stages)
// ---------------------------------------------------------------------------
__global__ void k_scanA() {
    __shared__ int s[256];
    int t = threadIdx.x;
    s[t] = g_hist[blockIdx.x * 256 + t];
    __syncthreads();
    for (int off = 128; off > 0; off >>= 1) {
        if (t < off) s[t] += s[t + off];
        __syncthreads();
    }
    if (t == 0) g_bsum[blockIdx.x] = s[0];
}

__global__ void k_scanB() {
    __shared__ int sh[256];
    int t = threadIdx.x;
    int own = g_bsum[255 - t];
    sh[t] = own;
    __syncthreads();
    for (int off = 1; off < 256; off <<= 1) {
        int v = (t >= off) ? sh[t - off] : 0;
        __syncthreads();
        sh[t] += v;
        __syncthreads();
    }
    g_boff[255 - t] = sh[t] - own;
}

__global__ void k_scanC() {
    __shared__ int sh[256];
    int t = threadIdx.x;
    int blk = blockIdx.x;
    int own = g_hist[blk * 256 + (255 - t)];
    sh[t] = own;
    __syncthreads();
    for (int off = 1; off < 256; off <<= 1) {
        int v = (t >= off) ? sh[t - off] : 0;
        __syncthreads();
        sh[t] += v;
        __syncthreads();
    }
    g_offs[blk * 256 + (255 - t)] = g_boff[blk] + sh[t] - own;
}

// ---------------------------------------------------------------------------
// 11) scatter into bucket slots
// ---------------------------------------------------------------------------
__global__ void k_scatter() {
    int i = blockIdx.x * blockDim.x + threadIdx.x;
    if (i >= NA) return;
    unsigned long long k = g_key[i];
    int b = (int)(k >> 48);
    int pos = g_offs[b] + atomicAdd(&g_cnt[b], 1);
    g_slotkey[pos] = k;
    g_slotidx[pos] = i;
}

// ---------------------------------------------------------------------------
// 12) exact within-bucket rank + gather top-NPRE boxes in sorted order
// ---------------------------------------------------------------------------
__global__ void k_fixup() {
    int p = blockIdx.x * blockDim.x + threadIdx.x;
    if (p >= NA) return;
    unsigned long long k = g_slotkey[p];
    int b = (int)(k >> 48);
    int off = g_offs[b];
    if (off >= NPRE) return;
    int n = g_hist[b];
    int r = off;
    for (int q = off; q < off + n; ++q)
        if (g_slotkey[q] > k) ++r;
    if (r < NPRE) {
        int idx = g_slotidx[p];
        g_sy1[r] = g_ry1[idx];
        g_sx1[r] = g_rx1[idx];
        g_sy2[r] = g_ry2[idx];
        g_sx2[r] = g_rx2[idx];
        g_svalid[r] = g_valid[idx];
    }
}

// ---------------------------------------------------------------------------
// 13) IoU bitmask, coalesced: block = box i; lane j-per-thread + ballot
//     writes 32-bit words directly. Exact ref math (unfused fp32).
// ---------------------------------------------------------------------------
__global__ void __launch_bounds__(256) k_mask() {
    int i = blockIdx.x;
    int tid = threadIdx.x;
    float y1 = g_sy1[i], x1 = g_sx1[i], y2 = g_sy2[i], x2 = g_sx2[i];
    float ai = __fmul_rn(__fsub_rn(y2, y1), __fsub_rn(x2, x1));
    int jb0 = i & ~255;           // 256-aligned; covers all words k_nms reads
    for (int jb = jb0; jb < NWORD32 * 32; jb += 256) {
        int j = jb + tid;
        bool over = false;
        if (j > i && j < NPRE) {
            float yy1 = g_sy1[j], xx1 = g_sx1[j], yy2 = g_sy2[j], xx2 = g_sx2[j];
            float ih = fmaxf(__fsub_rn(fminf(y2, yy2), fmaxf(y1, yy1)), 0.f);
            float iw = fmaxf(__fsub_rn(fminf(x2, xx2), fmaxf(x1, xx1)), 0.f);
            float inter = __fmul_rn(ih, iw);
            if (inter > 0.f) {
                float aj = __fmul_rn(__fsub_rn(yy2, yy1), __fsub_rn(xx2, xx1));
                float denom = __fadd_rn(__fsub_rn(__fadd_rn(ai, aj), inter), 1e-12f);
                over = (__fdiv_rn(inter, denom) > 0.7f);
            }
        }
        unsigned bal = __ballot_sync(0xFFFFFFFFu, over);
        if ((tid & 31) == 0)
            g_mask32[(size_t)i * NWORD32 + (jb >> 5) + (tid >> 5)] = bal;
    }
}

// ---------------------------------------------------------------------------
// 14) sequential greedy NMS scan (single block) + write rois / roi_indices
// ---------------------------------------------------------------------------
__global__ void __launch_bounds__(256) k_nms(float* __restrict__ out) {
    __shared__ unsigned long long rem[NWORD];
    __shared__ int s_i;
    int tid = threadIdx.x;
    for (int w = tid; w < NWORD; w += 256) rem[w] = 0ull;
    __syncthreads();
    if (tid == 0) rem[NWORD - 1] |= 0xFFFFFFFF00000000ull;  // tail beyond 12000
    __syncthreads();
    for (int i = tid; i < NPRE; i += 256)
        if (!g_svalid[i]) atomicOr(&rem[i >> 6], 1ull << (i & 63));
    __syncthreads();

    int nk = 0;
    for (int w = 0; w < NWORD; ++w) {
        while (true) {
            if (tid == 0) {
                unsigned long long avail = ~rem[w];
                if (avail == 0ull) {
                    s_i = -1;
                } else {
                    int b = __ffsll((long long)avail) - 1;
                    s_i = (w << 6) + b;
                    rem[w] |= (1ull << b);
                }
            }
            __syncthreads();
            int i = s_i;
            if (i < 0) break;
            if (tid < 4) {
                float v = (tid == 0) ? g_sy1[i]
                        : (tid == 1) ? g_sx1[i]
                        : (tid == 2) ? g_sy2[i] : g_sx2[i];
                out[OUT_ROIS + nk * 4 + tid] = v;
            }
            const unsigned long long* mrow =
                (const unsigned long long*)(g_mask32 + (size_t)i * NWORD32);
            for (int w2 = w + tid; w2 < NWORD; w2 += 256)
                rem[w2] |= mrow[w2];
            nk++;
            __syncthreads();
            if (nk >= NPOST) { w = NWORD; break; }
        }
    }
    // zero-fill remaining rois rows; roi_indices all zero (batch index 0)
    for (int r = nk * 4 + tid; r < NPOST * 4; r += 256) out[OUT_ROIS + r] = 0.f;
    for (int r = tid; r < NPOST; r += 256) out[OUT_IDX + r] = 0.f;
}

// ---------------------------------------------------------------------------
extern "C" void kernel_launch(void* const* d_in, const int* in_sizes, int n_in,
                              void* d_out, int out_size) {
    const float* x  = (const float*)d_in[0];
    const float* W1 = (const float*)d_in[1];
    const float* b1 = (const float*)d_in[2];
    const float* Ws = (const float*)d_in[3];
    const float* bs = (const float*)d_in[4];
    const float* Wl = (const float*)d_in[5];
    const float* bl = (const float*)d_in[6];
    float* out = (float*)d_out;

    k_wt<<<(CO * KDIM + 255) / 256, 256>>>(W1);
    k_pad<<<(CI * PADPIX + 255) / 256, 256>>>(x);
    k_conv1<<<dim3((NPIX + 31) / 32, CO / 32), 128>>>(b1);
    k_heads<<<(NPIX + 31) / 32, 256>>>(Wl, bl, Ws, bs, out);
    k_fg<<<(NA + 255) / 256, 256>>>(out);
    k_anchor<<<(NA + 255) / 256, 256>>>(out);
    k_zero<<<512, 256>>>();
    k_decode<<<(NA + 255) / 256, 256>>>(out);
    k_scanA<<<256, 256>>>();
    k_scanB<<<1, 256>>>();
    k_scanC<<<256, 256>>>();
    k_scatter<<<(NA + 255) / 256, 256>>>();
    k_fixup<<<(NA + 255) / 256, 256>>>();
    k_mask<<<NPRE, 256>>>();
    k_nms<<<1, 256>>>(out);
}

// round 17
// speedup vs baseline: 1.7717x; 1.7717x over previous
#include <cuda_runtime.h>
#include <cuda_bf16.h>
#include <math.h>

// ---------------------------------------------------------------------------
// Problem constants
// ---------------------------------------------------------------------------
#define CI      512
#define CO      512
#define HH      50
#define WW      50
#define NPIX    2500
#define HP      52
#define WP      52
#define PADPIX  2704          // 52*52
#define KDIM    4608          // 512*9
#define NA      22500         // 2500*9 anchors
#define NPRE    12000
#define NWORD   188           // ceil(12000/64) 64-bit words
#define NWORD32 376           // 32-bit words per mask row
#define NPOST   2000
#define NHEADOC 54            // 36 loc + 18 score channels

// output layout (flattened tuple, all f32):
// rpn_locs [22500,4] | rpn_scores [22500,2] | rois [2000,4] | roi_indices [2000] | anchor [22500,4]
#define OUT_LOCS   0
#define OUT_SCORES 90000
#define OUT_ROIS   135000
#define OUT_IDX    143000
#define OUT_ANCH   145000

// ---------------------------------------------------------------------------
// Scratch (__device__ globals — allocation is forbidden)
// ---------------------------------------------------------------------------
__device__ float g_xpad[CI * PADPIX];
__device__ float g_Wt[CO * KDIM];     // W1 transposed to [co][(ky*3+kx)*512+ci]
__device__ float g_h[CO * NPIX];
__device__ float g_fg[NA];
__device__ float g_ry1[NA], g_rx1[NA], g_ry2[NA], g_rx2[NA];
__device__ int   g_valid[NA];
__device__ unsigned long long g_key[NA];
__device__ int   g_hist[65536];
__device__ int   g_cnt[65536];
__device__ int   g_bsum[256];
__device__ int   g_boff[256];
__device__ int   g_offs[65536];
__device__ unsigned long long g_slotkey[NA];
__device__ int   g_slotidx[NA];
__device__ float g_sy1[NPRE], g_sx1[NPRE], g_sy2[NPRE], g_sx2[NPRE];
__device__ int   g_svalid[NPRE];
__device__ __align__(8) unsigned g_mask32[(size_t)NPRE * NWORD32];

// ---------------------------------------------------------------------------
// 0) transpose W1[co][ci][ky][kx] -> g_Wt[co][kyx*512+ci]  (im2col k-order)
// ---------------------------------------------------------------------------
__global__ void k_wt(const float* __restrict__ W1) {
    int i = blockIdx.x * blockDim.x + threadIdx.x;
    if (i >= CO * KDIM) return;
    int co = i / KDIM;
    int k  = i - co * KDIM;       // k' = kyx*512 + ci
    int kyx = k >> 9;
    int ci  = k & 511;
    g_Wt[i] = W1[co * KDIM + ci * 9 + kyx];
}

// ---------------------------------------------------------------------------
// 1) zero-pad input  x[512][50][50] -> g_xpad[512][52][52]
// ---------------------------------------------------------------------------
__global__ void k_pad(const float* __restrict__ x) {
    int idx = blockIdx.x * blockDim.x + threadIdx.x;
    if (idx >= CI * PADPIX) return;
    int ci = idx / PADPIX;
    int r  = idx - ci * PADPIX;
    int yy = r / WP;
    int xx = r - yy * WP;
    float v = 0.f;
    if (yy >= 1 && yy <= HH && xx >= 1 && xx <= WW)
        v = x[ci * NPIX + (yy - 1) * WW + (xx - 1)];
    g_xpad[idx] = v;
}

// ---------------------------------------------------------------------------
// 2) conv1 3x3 512->512, fp32 implicit GEMM + bias + ReLU.
//    NUMERICS (bit-identical to R15): per output, k' = (ky*3+kx)*512 + ci
//    ascending; 8 interleaved chains, chain = k' mod 8, sequential FMA
//    within chain; combine q_l = C_l + C_{l+4}; total = ((q0+q1)+q2)+q3.
//    PERF: 64co x 64px tile, 256 threads, 4co x 4px x 8 chains per thread,
//    register-staged global prefetch overlapping the FFMA phase.
// ---------------------------------------------------------------------------
__global__ void __launch_bounds__(256) k_conv1(const float* __restrict__ b1) {
    __shared__ float As[16][64];
    __shared__ float Bs[16][64];
    int t   = threadIdx.x;
    int pb  = blockIdx.x * 64;
    int cob = blockIdx.y * 64;
    int tco = (t >> 4) * 4;        // 0..60
    int tpx = (t & 15) * 4;        // 0..60
    int acol = t >> 2;             // A loader: co 0..63
    int akq  = (t & 3) << 2;       // A loader: k 0,4,8,12
    int bkl  = t >> 4;             // B loader: k 0..15
    int bps  = (t & 15) << 2;      // B loader: px seg 0..60

    float acc[4][4][8];
#pragma unroll
    for (int i = 0; i < 4; ++i)
#pragma unroll
        for (int j = 0; j < 4; ++j)
#pragma unroll
            for (int r = 0; r < 8; ++r) acc[i][j][r] = 0.f;

    // stage first slab into registers
    float4 areg;
    float  breg[4];
    {
        areg = *(const float4*)(g_Wt + (size_t)(cob + acol) * KDIM + 0 + akq);
        int ci = bkl;                              // kb=0: kyx=0, ky=kx=0
        const float* base = g_xpad + ci * PADPIX;
#pragma unroll
        for (int jj = 0; jj < 4; ++jj) {
            int p = pb + bps + jj;
            float v = 0.f;
            if (p < NPIX) {
                int y  = p / WW;
                int xx = p - y * WW;
                v = base[y * WP + xx];
            }
            breg[jj] = v;
        }
    }

    for (int kb = 0; kb < KDIM; kb += 16) {
        // commit staged slab to smem
        As[akq + 0][acol] = areg.x;
        As[akq + 1][acol] = areg.y;
        As[akq + 2][acol] = areg.z;
        As[akq + 3][acol] = areg.w;
        Bs[bkl][bps + 0] = breg[0];
        Bs[bkl][bps + 1] = breg[1];
        Bs[bkl][bps + 2] = breg[2];
        Bs[bkl][bps + 3] = breg[3];
        __syncthreads();
        // prefetch next slab (overlaps FFMA below)
        int kn = kb + 16;
        if (kn < KDIM) {
            areg = *(const float4*)(g_Wt + (size_t)(cob + acol) * KDIM + kn + akq);
            int kyx = kn >> 9;
            int ci  = (kn & 511) + bkl;
            int ky  = kyx / 3;
            int kx  = kyx - ky * 3;
            const float* base = g_xpad + ci * PADPIX + ky * WP + kx;
#pragma unroll
            for (int jj = 0; jj < 4; ++jj) {
                int p = pb + bps + jj;
                float v = 0.f;
                if (p < NPIX) {
                    int y  = p / WW;
                    int xx = p - y * WW;
                    v = base[y * WP + xx];
                }
                breg[jj] = v;
            }
        }
#pragma unroll
        for (int kk = 0; kk < 16; ++kk) {
            float4 av = *(const float4*)&As[kk][tco];
            float4 bv = *(const float4*)&Bs[kk][tpx];
            const int r = kk & 7;      // chain id = k' mod 8 (kb % 16 == 0)
            float a[4] = {av.x, av.y, av.z, av.w};
            float b[4] = {bv.x, bv.y, bv.z, bv.w};
#pragma unroll
            for (int i = 0; i < 4; ++i)
#pragma unroll
                for (int j = 0; j < 4; ++j)
                    acc[i][j][r] = __fmaf_rn(a[i], b[j], acc[i][j][r]);
        }
        __syncthreads();
    }
#pragma unroll
    for (int i = 0; i < 4; ++i) {
        int co = cob + tco + i;
        float bb = b1[co];
#pragma unroll
        for (int j = 0; j < 4; ++j) {
            int pg = pb + tpx + j;
            if (pg < NPIX) {
                float q0 = __fadd_rn(acc[i][j][0], acc[i][j][4]);
                float q1 = __fadd_rn(acc[i][j][1], acc[i][j][5]);
                float q2 = __fadd_rn(acc[i][j][2], acc[i][j][6]);
                float q3 = __fadd_rn(acc[i][j][3], acc[i][j][7]);
                float s  = __fadd_rn(__fadd_rn(__fadd_rn(q0, q1), q2), q3);
                float v  = __fadd_rn(s, bb);
                g_h[(size_t)co * NPIX + pg] = fmaxf(v, 0.f);
            }
        }
    }
}

// ---------------------------------------------------------------------------
// 3) 1x1 heads: one thread per (px, oc). Same 8-chain interleave over ci
//    (chain = ci mod 8), same combine — bit-identical to R15.
// ---------------------------------------------------------------------------
__global__ void __launch_bounds__(256) k_heads(const float* __restrict__ Wl,
                                               const float* __restrict__ bl,
                                               const float* __restrict__ Ws,
                                               const float* __restrict__ bs,
                                               float* __restrict__ out) {
    int tx = threadIdx.x & 31;
    int ty = threadIdx.x >> 5;                 // 0..7
    int px = blockIdx.x * 32 + tx;
    int oc = blockIdx.y * 8 + ty;
    if (oc >= NHEADOC || px >= NPIX) return;

    const float* Wp = (oc < 36) ? (Wl + oc * CO) : (Ws + (oc - 36) * CO);
    float acc[8];
#pragma unroll
    for (int r = 0; r < 8; ++r) acc[r] = 0.f;

    const float* hp = g_h + px;
#pragma unroll 4
    for (int c0 = 0; c0 < CO; c0 += 8) {
#pragma unroll
        for (int r = 0; r < 8; ++r) {
            float hv = hp[(size_t)(c0 + r) * NPIX];
            float wv = __ldg(Wp + c0 + r);
            acc[r] = __fmaf_rn(hv, wv, acc[r]);
        }
    }
    float q0 = __fadd_rn(acc[0], acc[4]);
    float q1 = __fadd_rn(acc[1], acc[5]);
    float q2 = __fadd_rn(acc[2], acc[6]);
    float q3 = __fadd_rn(acc[3], acc[7]);
    float sum = __fadd_rn(__fadd_rn(__fadd_rn(q0, q1), q2), q3);
    if (oc < 36) {
        float v = __fadd_rn(sum, bl[oc]);
        int a = oc >> 2, j = oc & 3;
        out[OUT_LOCS + (px * 9 + a) * 4 + j] = v;
    } else {
        int sdx = oc - 36;
        float v = __fadd_rn(sum, bs[sdx]);
        int a = sdx >> 1, b2 = sdx & 1;
        out[OUT_SCORES + (px * 9 + a) * 2 + b2] = v;
    }
}

// ---------------------------------------------------------------------------
// 4) softmax fg scores
// ---------------------------------------------------------------------------
__global__ void k_fg(const float* __restrict__ out) {
    int i = blockIdx.x * blockDim.x + threadIdx.x;
    if (i >= NA) return;
    float s0 = out[OUT_SCORES + 2 * i];
    float s1 = out[OUT_SCORES + 2 * i + 1];
    float m = fmaxf(s0, s1);
    float e0 = expf(__fsub_rn(s0, m));
    float e1 = expf(__fsub_rn(s1, m));
    g_fg[i] = __fdiv_rn(e1, __fadd_rn(e0, e1));
}

// ---------------------------------------------------------------------------
// 5) anchors (fp64 to bit-match numpy's promotion chain)
// ---------------------------------------------------------------------------
__global__ void k_anchor(float* __restrict__ out) {
    int i = blockIdx.x * blockDim.x + threadIdx.x;
    if (i >= NA) return;
    int p = i / 9, a = i - p * 9;
    int y = p / WW, x = p - y * WW;
    int ra = a / 3, sc = a - ra * 3;
    double ratio = (ra == 0) ? 0.5 : (ra == 1) ? 1.0 : 2.0;
    double scale = (sc == 0) ? 8.0 : (sc == 1) ? 16.0 : 32.0;
    double hh_ = 16.0 * scale * sqrt(ratio);
    double ww_ = 16.0 * scale * sqrt(1.0 / ratio);
    float b0  = (float)(8.0 - hh_ * 0.5);
    float b1_ = (float)(8.0 - ww_ * 0.5);
    float b2  = (float)(8.0 + hh_ * 0.5);
    float b3  = (float)(8.0 + ww_ * 0.5);
    double sy = (double)(y * 16);
    double sx = (double)(x * 16);
    out[OUT_ANCH + i * 4 + 0] = (float)(sy + (double)b0);
    out[OUT_ANCH + i * 4 + 1] = (float)(sx + (double)b1_);
    out[OUT_ANCH + i * 4 + 2] = (float)(sy + (double)b2);
    out[OUT_ANCH + i * 4 + 3] = (float)(sx + (double)b3);
}

// ---------------------------------------------------------------------------
// 6) zero histograms
// ---------------------------------------------------------------------------
__global__ void k_zero() {
    int i = blockIdx.x * blockDim.x + threadIdx.x;
    if (i < 65536) { g_hist[i] = 0; g_cnt[i] = 0; }
}

// ---------------------------------------------------------------------------
// 7) decode boxes + clip + valid + sort keys + histogram.
// ---------------------------------------------------------------------------
__global__ void k_decode(const float* __restrict__ out) {
    int i = blockIdx.x * blockDim.x + threadIdx.x;
    if (i >= NA) return;
    float a0 = out[OUT_ANCH + i * 4 + 0];
    float a1 = out[OUT_ANCH + i * 4 + 1];
    float a2 = out[OUT_ANCH + i * 4 + 2];
    float a3 = out[OUT_ANCH + i * 4 + 3];
    float dy = out[OUT_LOCS + i * 4 + 0];
    float dx = out[OUT_LOCS + i * 4 + 1];
    float dh = out[OUT_LOCS + i * 4 + 2];
    float dw = out[OUT_LOCS + i * 4 + 3];
    float sh = __fsub_rn(a2, a0);
    float sw = __fsub_rn(a3, a1);
    float cy = __fadd_rn(a0, __fmul_rn(0.5f, sh));
    float cx = __fadd_rn(a1, __fmul_rn(0.5f, sw));
    float ncy = __fadd_rn(__fmul_rn(dy, sh), cy);
    float ncx = __fadd_rn(__fmul_rn(dx, sw), cx);
    float nh = __fmul_rn(expf(dh), sh);
    float nw = __fmul_rn(expf(dw), sw);
    float y1 = __fsub_rn(ncy, __fmul_rn(0.5f, nh));
    float x1 = __fsub_rn(ncx, __fmul_rn(0.5f, nw));
    float y2 = __fadd_rn(ncy, __fmul_rn(0.5f, nh));
    float x2 = __fadd_rn(ncx, __fmul_rn(0.5f, nw));
    y1 = fminf(fmaxf(y1, 0.f), 800.f);
    x1 = fminf(fmaxf(x1, 0.f), 800.f);
    y2 = fminf(fmaxf(y2, 0.f), 800.f);
    x2 = fminf(fmaxf(x2, 0.f), 800.f);
    float hsz = __fsub_rn(y2, y1);
    float wsz = __fsub_rn(x2, x1);
    int valid = (hsz >= 16.f) && (wsz >= 16.f);
    g_ry1[i] = y1; g_rx1[i] = x1; g_ry2[i] = y2; g_rx2[i] = x2;
    g_valid[i] = valid;
    unsigned mf;
    if (valid) {
        unsigned f = __float_as_uint(g_fg[i]);
        mf = (f & 0x80000000u) ? ~f : (f | 0x80000000u);
    } else {
        mf = 0x40000000u - ((unsigned)i << 11);   // descending in i, < all valid
    }
    unsigned long long key =
        ((unsigned long long)mf << 32) | (unsigned long long)(NA - 1 - i);
    g_key[i] = key;
    atomicAdd(&g_hist[mf >> 16], 1);
}

// ---------------------------------------------------------------------------
// 8-10) descending exclusive scan of 65536-bucket histogram (3 stages)
// ---------------------------------------------------------------------------
__global__ void k_scanA() {
    __shared__ int s[256];
    int t = threadIdx.x;
    s[t] = g_hist[blockIdx.x * 256 + t];
    __syncthreads();
    for (int off = 128; off > 0; off >>= 1) {
        if (t < off) s[t] += s[t + off];
        __syncthreads();
    }
    if (t == 0) g_bsum[blockIdx.x] = s[0];
}

__global__ void k_scanB() {
    __shared__ int sh[256];
    int t = threadIdx.x;
    int own = g_bsum[255 - t];
    sh[t] = own;
    __syncthreads();
    for (int off = 1; off < 256; off <<= 1) {
        int v = (t >= off) ? sh[t - off] : 0;
        __syncthreads();
        sh[t] += v;
        __syncthreads();
    }
    g_boff[255 - t] = sh[t] - own;
}

__global__ void k_scanC() {
    __shared__ int sh[256];
    int t = threadIdx.x;
    int blk = blockIdx.x;
    int own = g_hist[blk * 256 + (255 - t)];
    sh[t] = own;
    __syncthreads();
    for (int off = 1; off < 256; off <<= 1) {
        int v = (t >= off) ? sh[t - off] : 0;
        __syncthreads();
        sh[t] += v;
        __syncthreads();
    }
    g_offs[blk * 256 + (255 - t)] = g_boff[blk] + sh[t] - own;
}

// ---------------------------------------------------------------------------
// 11) scatter into bucket slots
// ---------------------------------------------------------------------------
__global__ void k_scatter() {
    int i = blockIdx.x * blockDim.x + threadIdx.x;
    if (i >= NA) return;
    unsigned long long k = g_key[i];
    int b = (int)(k >> 48);
    int pos = g_offs[b] + atomicAdd(&g_cnt[b], 1);
    g_slotkey[pos] = k;
    g_slotidx[pos] = i;
}

// ---------------------------------------------------------------------------
// 12) exact within-bucket rank + gather top-NPRE boxes in sorted order
// ---------------------------------------------------------------------------
__global__ void k_fixup() {
    int p = blockIdx.x * blockDim.x + threadIdx.x;
    if (p >= NA) return;
    unsigned long long k = g_slotkey[p];
    int b = (int)(k >> 48);
    int off = g_offs[b];
    if (off >= NPRE) return;
    int n = g_hist[b];
    int r = off;
    for (int q = off; q < off + n; ++q)
        if (g_slotkey[q] > k) ++r;
    if (r < NPRE) {
        int idx = g_slotidx[p];
        g_sy1[r] = g_ry1[idx];
        g_sx1[r] = g_rx1[idx];
        g_sy2[r] = g_ry2[idx];
        g_sx2[r] = g_rx2[idx];
        g_svalid[r] = g_valid[idx];
    }
}

// ---------------------------------------------------------------------------
// 13) IoU bitmask, coalesced: block = box i; lane j-per-thread + ballot
//     writes 32-bit words directly. Exact ref math (unfused fp32).
// ---------------------------------------------------------------------------
__global__ void __launch_bounds__(256) k_mask() {
    int i = blockIdx.x;
    int tid = threadIdx.x;
    float y1 = g_sy1[i], x1 = g_sx1[i], y2 = g_sy2[i], x2 = g_sx2[i];
    float ai = __fmul_rn(__fsub_rn(y2, y1), __fsub_rn(x2, x1));
    int jb0 = i & ~255;           // 256-aligned; covers all words k_nms reads
    for (int jb = jb0; jb < NWORD32 * 32; jb += 256) {
        int j = jb + tid;
        bool over = false;
        if (j > i && j < NPRE) {
            float yy1 = g_sy1[j], xx1 = g_sx1[j], yy2 = g_sy2[j], xx2 = g_sx2[j];
            float ih = fmaxf(__fsub_rn(fminf(y2, yy2), fmaxf(y1, yy1)), 0.f);
            float iw = fmaxf(__fsub_rn(fminf(x2, xx2), fmaxf(x1, xx1)), 0.f);
            float inter = __fmul_rn(ih, iw);
            if (inter > 0.f) {
                float aj = __fmul_rn(__fsub_rn(yy2, yy1), __fsub_rn(xx2, xx1));
                float denom = __fadd_rn(__fsub_rn(__fadd_rn(ai, aj), inter), 1e-12f);
                over = (__fdiv_rn(inter, denom) > 0.7f);
            }
        }
        unsigned bal = __ballot_sync(0xFFFFFFFFu, over);
        if ((tid & 31) == 0)
            g_mask32[(size_t)i * NWORD32 + (jb >> 5) + (tid >> 5)] = bal;
    }
}

// ---------------------------------------------------------------------------
// 14) word-batched greedy NMS (single block). Identical keep set/order to
//     the sequential scan: per 64-bit word, prefetch candidates' own-word
//     mask entries, resolve intra-word suppression serially from smem,
//     then batch-OR kept rows into rem[w+1..] with all 256 threads.
// ---------------------------------------------------------------------------
__global__ void __launch_bounds__(256) k_nms(float* __restrict__ out) {
    __shared__ unsigned long long rem[NWORD];
    __shared__ unsigned long long mword[64];
    __shared__ int kept[64];
    __shared__ int s_nk;
    __shared__ int s_total;
    int tid = threadIdx.x;
    for (int w = tid; w < NWORD; w += 256) rem[w] = 0ull;
    if (tid == 0) s_total = 0;
    __syncthreads();
    if (tid == 0) rem[NWORD - 1] |= 0xFFFFFFFF00000000ull;  // tail beyond 12000
    __syncthreads();
    for (int i = tid; i < NPRE; i += 256)
        if (!g_svalid[i]) atomicOr(&rem[i >> 6], 1ull << (i & 63));
    __syncthreads();

    for (int w = 0; w < NWORD; ++w) {
        unsigned long long avail = ~rem[w];
        if (!avail) continue;
        // prefetch candidates' own-word mask entry (parallel, one L2 trip)
        if (tid < 64 && ((avail >> tid) & 1ull))
            mword[tid] = ((const unsigned long long*)
                          (g_mask32 + (size_t)((w << 6) + tid) * NWORD32))[w];
        __syncthreads();
        // serial intra-word resolution (registers + smem only)
        if (tid == 0) {
            unsigned long long cur = rem[w];
            int nk = 0, tot = s_total;
            unsigned long long av = ~cur;
            while (av) {
                int b = __ffsll((long long)av) - 1;
                kept[nk++] = (w << 6) + b;
                cur |= (1ull << b);
                cur |= mword[b];          // row's own-word bits (all j > b)
                av = ~cur;
                if (tot + nk >= NPOST) break;
            }
            rem[w] = cur;
            s_nk = nk;
        }
        __syncthreads();
        int nk  = s_nk;
        int tot = s_total;
        // write rois for this word's keeps
        for (int idx = tid; idx < nk * 4; idx += 256) {
            int r = idx >> 2, c = idx & 3, i = kept[r];
            float v = (c == 0) ? g_sy1[i]
                    : (c == 1) ? g_sx1[i]
                    : (c == 2) ? g_sy2[i] : g_sx2[i];
            out[OUT_ROIS + (tot + r) * 4 + c] = v;
        }
        bool done = (tot + nk >= NPOST);
        // batch-OR kept rows into rem[w+1..] (each word owned by one thread)
        if (!done && nk > 0) {
            for (int w2 = w + 1 + tid; w2 < NWORD; w2 += 256) {
                unsigned long long v = rem[w2];
                for (int r = 0; r < nk; ++r)
                    v |= ((const unsigned long long*)
                          (g_mask32 + (size_t)kept[r] * NWORD32))[w2];
                rem[w2] = v;
            }
        }
        if (tid == 0) s_total = tot + nk;
        __syncthreads();
        if (done) break;
    }
    __syncthreads();
    int total = s_total;
    if (total > NPOST) total = NPOST;
    // zero-fill remaining rois rows; roi_indices all zero (batch index 0)
    for (int r = total * 4 + tid; r < NPOST * 4; r += 256) out[OUT_ROIS + r] = 0.f;
    for (int r = tid; r < NPOST; r += 256) out[OUT_IDX + r] = 0.f;
}

// ---------------------------------------------------------------------------
extern "C" void kernel_launch(void* const* d_in, const int* in_sizes, int n_in,
                              void* d_out, int out_size) {
    const float* x  = (const float*)d_in[0];
    const float* W1 = (const float*)d_in[1];
    const float* b1 = (const float*)d_in[2];
    const float* Ws = (const float*)d_in[3];
    const float* bs = (const float*)d_in[4];
    const float* Wl = (const float*)d_in[5];
    const float* bl = (const float*)d_in[6];
    float* out = (float*)d_out;

    k_wt<<<(CO * KDIM + 255) / 256, 256>>>(W1);
    k_pad<<<(CI * PADPIX + 255) / 256, 256>>>(x);
    k_conv1<<<dim3((NPIX + 63) / 64, CO / 64), 256>>>(b1);
    k_heads<<<dim3((NPIX + 31) / 32, (NHEADOC + 7) / 8), 256>>>(Wl, bl, Ws, bs, out);
    k_fg<<<(NA + 255) / 256, 256>>>(out);
    k_anchor<<<(NA + 255) / 256, 256>>>(out);
    k_zero<<<512, 256>>>();
    k_decode<<<(NA + 255) / 256, 256>>>(out);
    k_scanA<<<256, 256>>>();
    k_scanB<<<1, 256>>>();
    k_scanC<<<256, 256>>>();
    k_scatter<<<(NA + 255) / 256, 256>>>();
    k_fixup<<<(NA + 255) / 256, 256>>>();
    k_mask<<<NPRE, 256>>>();
    k_nms<<<1, 256>>>(out);
}